// round 14
// baseline (speedup 1.0000x reference)
#include <cuda_runtime.h>
#include <cuda_bf16.h>
#include <math.h>
#include <stdint.h>

// Shapes (fixed by the problem)
#define B_ 4
#define T_ 1024
#define C_ 1024
#define H_ 16
#define D_ 64
#define L3C (3 * C_)          // 3072
#define NPOS (2 * T_ - 1)     // 2047

// Scratch (allocation-free rule: __device__ globals)
__device__ float g_qkv[(size_t)B_ * T_ * L3C];   // (B*T, 3C) row-major
__device__ float g_attn[(size_t)B_ * T_ * C_];   // (B*T, C) row-major
__device__ float g_table[NPOS * H_];             // (2L-1, H), pre-scaled by log2(e)

__device__ __forceinline__ uint32_t f2tf32(float x) {
    uint32_t u;
    asm("cvt.rna.tf32.f32 %0, %1;" : "=r"(u) : "f"(x));
    return u;
}
__device__ __forceinline__ float tf32rf(float x) { return __uint_as_float(f2tf32(x)); }

__device__ __forceinline__ float ex2f(float x) {
    float y;
    asm("ex2.approx.f32 %0, %1;" : "=f"(y) : "f"(x));
    return y;
}

__device__ __forceinline__ void mma_tf32(float* d, const uint32_t* a,
                                         uint32_t b0, uint32_t b1) {
    asm volatile(
        "mma.sync.aligned.m16n8k8.row.col.f32.tf32.tf32.f32 "
        "{%0,%1,%2,%3}, {%4,%5,%6,%7}, {%8,%9}, {%0,%1,%2,%3};\n"
        : "+f"(d[0]), "+f"(d[1]), "+f"(d[2]), "+f"(d[3])
        : "r"(a[0]), "r"(a[1]), "r"(a[2]), "r"(a[3]), "r"(b0), "r"(b1));
}

__device__ __forceinline__ void ldsm4(uint32_t* r, uint32_t saddr) {
    asm volatile(
        "ldmatrix.sync.aligned.m8n8.x4.shared.b16 {%0,%1,%2,%3}, [%4];\n"
        : "=r"(r[0]), "=r"(r[1]), "=r"(r[2]), "=r"(r[3]) : "r"(saddr));
}

// ---------------------------------------------------------------------------
// Kernel 1: reduce rel_pos_emb (2047,1024) -> table (2047,16), × log2(e)
// ---------------------------------------------------------------------------
__global__ __launch_bounds__(512) void reduce_table_kernel(const float* __restrict__ rel) {
    int row = blockIdx.x;
    int w   = threadIdx.x >> 5;
    int lane = threadIdx.x & 31;
    const float* p = rel + (size_t)row * C_ + w * D_;
    float s = p[lane] + p[lane + 32];
    #pragma unroll
    for (int off = 16; off > 0; off >>= 1)
        s += __shfl_xor_sync(0xffffffffu, s, off);
    if (lane == 0) g_table[row * H_ + w] = s * 1.4426950408889634f;
}

// ---------------------------------------------------------------------------
// Kernel 2: TF32 GEMM  C[M,N] = A[M,K] @ Bmat[N,K]^T + bias[N]
// CTA tile 128x128, 128 threads (4 warps, 2m x 2n), warp tile 64x64.
// TBK=16, register-prefetch double buffer, smem stride 20 floats
// (ldmatrix + STS conflict-free). 2 CTAs/SM: independent barrier domains
// overlap staging/barrier of one CTA with MMA of the other.
// ---------------------------------------------------------------------------
#define TBM 128
#define TBN 128
#define TBK 16
#define GST 20
#define A_FLOATS (TBM * GST)               // 2560 floats per stage
#define B_FLOATS (TBN * GST)               // 2560 floats per stage
#define STG_FLOATS (A_FLOATS + B_FLOATS)   // 5120
#define GEMM_SMEM (2 * STG_FLOATS * 4)     // 40960 B

__global__ __launch_bounds__(128, 2) void gemm_tf32_nt_bias(
    const float* __restrict__ A, const float* __restrict__ Bm,
    const float* __restrict__ bias, float* __restrict__ Cout,
    int M, int N, int K)
{
    extern __shared__ float gsm[];
    const uint32_t smBase = (uint32_t)__cvta_generic_to_shared(gsm);

    const int tid  = threadIdx.x;
    const int lane = tid & 31;
    const int wid  = tid >> 5;
    const int wm   = (wid & 1) * 64;      // 2 warps in m
    const int wn   = (wid >> 1) * 64;     // 2 warps in n
    const int m0   = blockIdx.y * TBM;
    const int n0   = blockIdx.x * TBN;

    const int qr = lane >> 2;
    const int qc = lane & 3;

    // loader: thread owns full 16-float k-slice of row tid for A and B
    const float* Aptr = A  + (size_t)(m0 + tid) * K;
    const float* Bptr = Bm + (size_t)(n0 + tid) * K;

    float* As = gsm;                       // [row][k] stride GST
    float* Bs = gsm + A_FLOATS;

    // fragment base addresses (stage 0, bytes)
    const uint32_t aAddr = smBase + (((wm + (lane & 15)) * GST + (lane >> 4) * 4) << 2);
    const uint32_t bRow = (lane & 7) + ((lane >> 4) & 1) * 8;
    const uint32_t bCol = ((lane >> 3) & 1) * 4;
    uint32_t bAddr[4];
    #pragma unroll
    for (int g = 0; g < 4; g++)
        bAddr[g] = smBase + (A_FLOATS << 2)
                 + (((wn + 16 * g + bRow) * GST + bCol) << 2);

    float acc[4][8][4];
    #pragma unroll
    for (int i = 0; i < 4; i++)
        #pragma unroll
        for (int j = 0; j < 8; j++)
            #pragma unroll
            for (int r = 0; r < 4; r++) acc[i][j][r] = 0.f;

    float4 fa[4], fb[4];
    // prefetch tile 0
    #pragma unroll
    for (int j = 0; j < 4; j++) {
        fa[j] = *(const float4*)(Aptr + j * 4);
        fb[j] = *(const float4*)(Bptr + j * 4);
    }
    // store tile 0 (tf32-rounded)
    #pragma unroll
    for (int j = 0; j < 4; j++) {
        float* da = &As[tid * GST + j * 4];
        da[0] = tf32rf(fa[j].x); da[1] = tf32rf(fa[j].y);
        da[2] = tf32rf(fa[j].z); da[3] = tf32rf(fa[j].w);
        float* db = &Bs[tid * GST + j * 4];
        db[0] = tf32rf(fb[j].x); db[1] = tf32rf(fb[j].y);
        db[2] = tf32rf(fb[j].z); db[3] = tf32rf(fb[j].w);
    }
    __syncthreads();

    const int nIter = K / TBK;
    for (int t = 0; t < nIter; t++) {
        const int buf = t & 1;
        const uint32_t bo = (uint32_t)buf * (STG_FLOATS * 4);
        if (t + 1 < nIter) {
            const float* ap = Aptr + (t + 1) * TBK;
            const float* bp = Bptr + (t + 1) * TBK;
            #pragma unroll
            for (int j = 0; j < 4; j++) {
                fa[j] = *(const float4*)(ap + j * 4);
                fb[j] = *(const float4*)(bp + j * 4);
            }
        }

        #pragma unroll
        for (int ks = 0; ks < 2; ks++) {
            const uint32_t ko = bo + ks * 32;
            uint32_t af[4][4], bf[4][4];
            #pragma unroll
            for (int ms = 0; ms < 4; ms++)
                ldsm4(af[ms], aAddr + (uint32_t)(ms * 16 * GST * 4) + ko);
            #pragma unroll
            for (int g = 0; g < 4; g++) ldsm4(bf[g], bAddr[g] + ko);
            #pragma unroll
            for (int ms = 0; ms < 4; ms++)
                #pragma unroll
                for (int g = 0; g < 4; g++) {
                    mma_tf32(acc[ms][2 * g],     af[ms], bf[g][0], bf[g][1]);
                    mma_tf32(acc[ms][2 * g + 1], af[ms], bf[g][2], bf[g][3]);
                }
        }

        if (t + 1 < nIter) {
            const int nb = buf ^ 1;
            float* Asn = gsm + nb * STG_FLOATS;
            float* Bsn = Asn + A_FLOATS;
            #pragma unroll
            for (int j = 0; j < 4; j++) {
                float* da = &Asn[tid * GST + j * 4];
                da[0] = tf32rf(fa[j].x); da[1] = tf32rf(fa[j].y);
                da[2] = tf32rf(fa[j].z); da[3] = tf32rf(fa[j].w);
                float* db = &Bsn[tid * GST + j * 4];
                db[0] = tf32rf(fb[j].x); db[1] = tf32rf(fb[j].y);
                db[2] = tf32rf(fb[j].z); db[3] = tf32rf(fb[j].w);
            }
        }
        __syncthreads();
    }

    // epilogue: + bias, write (float2 stores)
    #pragma unroll
    for (int ms = 0; ms < 4; ms++) {
        int r = m0 + wm + ms * 16 + qr;
        #pragma unroll
        for (int ns = 0; ns < 8; ns++) {
            int c = n0 + wn + ns * 8 + qc * 2;
            float b0 = bias[c], b1 = bias[c + 1];
            float2 v0 = make_float2(acc[ms][ns][0] + b0, acc[ms][ns][1] + b1);
            float2 v1 = make_float2(acc[ms][ns][2] + b0, acc[ms][ns][3] + b1);
            *(float2*)&Cout[(size_t)r * N + c]       = v0;
            *(float2*)&Cout[(size_t)(r + 8) * N + c] = v1;
        }
    }
}

// ---------------------------------------------------------------------------
// Kernel 3: TF32 MMA flash attention v2 (R8 verbatim — known good ~95us)
// ---------------------------------------------------------------------------
#define FST2 68
#define FOFF_KS 0
#define FOFF_VT (64 * FST2)
#define FOFF_QP (2 * 64 * FST2)
#define FOFF_SB (FOFF_QP + 128 * FST2)
#define FLASH2_FLOATS (FOFF_SB + 192)

__global__ __launch_bounds__(256, 2) void flash_mma2_kernel(float* __restrict__ out) {
    extern __shared__ float sm[];
    float* Ks = sm + FOFF_KS;
    float* Vt = sm + FOFF_VT;
    float* QP = sm + FOFF_QP;
    float* sb = sm + FOFF_SB;

    const int bh = blockIdx.y;
    const int b  = bh >> 4;
    const int h  = bh & 15;
    const int m0 = blockIdx.x * 128;

    const int tid  = threadIdx.x;
    const int lane = tid & 31;
    const int wid  = tid >> 5;
    const int qr = lane >> 2;
    const int qc = lane & 3;
    const int wm = wid * 16;

    {
        const float qsc = 0.125f * 1.4426950408889634f;
        const float* qb = g_qkv + (size_t)(b * T_ + m0) * L3C + h * D_;
        #pragma unroll
        for (int i = 0; i < 8; i++) {
            int f = tid + i * 256;
            int row = f >> 4, c4 = (f & 15) * 4;
            float4 v = *(const float4*)(qb + (size_t)row * L3C + c4);
            float4 w = make_float4(tf32rf(v.x * qsc), tf32rf(v.y * qsc),
                                   tf32rf(v.z * qsc), tf32rf(v.w * qsc));
            *(float4*)&QP[row * FST2 + c4] = w;
        }
    }
    __syncthreads();

    const uint32_t aAddr = (uint32_t)__cvta_generic_to_shared(QP)
        + (((wm + (lane & 15)) * FST2 + (lane >> 4) * 4) << 2);
    uint32_t qf[8][4];
    #pragma unroll
    for (int kb = 0; kb < 8; kb++) ldsm4(qf[kb], aAddr + kb * 32);

    const uint32_t bRow = (lane & 7) + ((lane >> 4) & 1) * 8;
    const uint32_t bCol = ((lane >> 3) & 1) * 4;
    uint32_t kAddr[4], vAddr[4];
    {
        const uint32_t kBase = (uint32_t)__cvta_generic_to_shared(Ks);
        const uint32_t vBase = (uint32_t)__cvta_generic_to_shared(Vt);
        #pragma unroll
        for (int g = 0; g < 4; g++) {
            kAddr[g] = kBase + (((16 * g + bRow) * FST2 + bCol) << 2);
            vAddr[g] = vBase + (((16 * g + bRow) * FST2 + bCol) << 2);
        }
    }

    float m_i[2] = {-1e30f, -1e30f};
    float l_i[2] = {0.f, 0.f};
    float o[8][4];
    #pragma unroll
    for (int ns = 0; ns < 8; ns++)
        #pragma unroll
        for (int r = 0; r < 4; r++) o[ns][r] = 0.f;

    const float* kgb = g_qkv + (size_t)(b * T_) * L3C + C_ + h * D_;
    const float* vgb = kgb + C_;

    const int ntiles = 2 * blockIdx.x + 2;
    for (int t = 0; t < ntiles; t++) {
        const int j0 = t * 64;
        #pragma unroll
        for (int i = 0; i < 4; i++) {
            int f = tid + i * 256;
            int row = f >> 4, c4 = (f & 15) * 4;
            float4 kv = *(const float4*)(kgb + (size_t)(j0 + row) * L3C + c4);
            float4 w = make_float4(tf32rf(kv.x), tf32rf(kv.y), tf32rf(kv.z), tf32rf(kv.w));
            *(float4*)&Ks[row * FST2 + c4] = w;
        }
        {
            const int d  = tid & 63;
            const int kq = tid >> 6;
            #pragma unroll
            for (int c = 0; c < 4; c++) {
                int key4 = kq * 4 + c * 16;
                const float* vp = vgb + (size_t)(j0 + key4) * L3C + d;
                float4 w = make_float4(tf32rf(vp[0]),
                                       tf32rf(vp[(size_t)L3C]),
                                       tf32rf(vp[(size_t)2 * L3C]),
                                       tf32rf(vp[(size_t)3 * L3C]));
                *(float4*)&Vt[d * FST2 + key4] = w;
            }
        }
        if (tid < 191) sb[tid] = g_table[(m0 - j0 + 960 + tid) * H_ + h];
        __syncthreads();

        const int rel = j0 - m0;
        if (rel <= wm + 15) {
            float sacc[8][4];
            #pragma unroll
            for (int ns = 0; ns < 8; ns++)
                #pragma unroll
                for (int r = 0; r < 4; r++) sacc[ns][r] = 0.f;

            #pragma unroll
            for (int kb = 0; kb < 8; kb++) {
                uint32_t bf[4][4];
                #pragma unroll
                for (int g = 0; g < 4; g++) ldsm4(bf[g], kAddr[g] + kb * 32);
                #pragma unroll
                for (int g = 0; g < 4; g++) {
                    mma_tf32(sacc[2 * g],     qf[kb], bf[g][0], bf[g][1]);
                    mma_tf32(sacc[2 * g + 1], qf[kb], bf[g][2], bf[g][3]);
                }
            }

            const bool tail = (rel >= 0);
            #pragma unroll
            for (int hl = 0; hl < 2; hl++) {
                const int rloc = wm + qr + hl * 8;
                float mx = -1e30f;
                #pragma unroll
                for (int ns = 0; ns < 8; ns++) {
                    #pragma unroll
                    for (int j2 = 0; j2 < 2; j2++) {
                        int col = ns * 8 + qc * 2 + j2;
                        float v = sacc[ns][hl * 2 + j2] + sb[rloc - col + 63];
                        if (tail && col + rel > rloc) v = -1e30f;
                        sacc[ns][hl * 2 + j2] = v;
                        mx = fmaxf(mx, v);
                    }
                }
                mx = fmaxf(mx, __shfl_xor_sync(0xffffffffu, mx, 1));
                mx = fmaxf(mx, __shfl_xor_sync(0xffffffffu, mx, 2));
                float mnew = fmaxf(m_i[hl], mx);
                float corr = ex2f(m_i[hl] - mnew);
                float rs = 0.f;
                #pragma unroll
                for (int ns = 0; ns < 8; ns++) {
                    #pragma unroll
                    for (int j2 = 0; j2 < 2; j2++) {
                        float p = ex2f(sacc[ns][hl * 2 + j2] - mnew);
                        sacc[ns][hl * 2 + j2] = p;
                        rs += p;
                    }
                }
                rs += __shfl_xor_sync(0xffffffffu, rs, 1);
                rs += __shfl_xor_sync(0xffffffffu, rs, 2);
                l_i[hl] = l_i[hl] * corr + rs;
                m_i[hl] = mnew;
                #pragma unroll
                for (int ns = 0; ns < 8; ns++) {
                    o[ns][hl * 2 + 0] *= corr;
                    o[ns][hl * 2 + 1] *= corr;
                }
            }

            {
                float* Pw = QP + wm * FST2;
                #pragma unroll
                for (int ns = 0; ns < 8; ns++) {
                    float2 p0 = make_float2(tf32rf(sacc[ns][0]), tf32rf(sacc[ns][1]));
                    float2 p1 = make_float2(tf32rf(sacc[ns][2]), tf32rf(sacc[ns][3]));
                    *(float2*)&Pw[qr * FST2 + ns * 8 + qc * 2] = p0;
                    *(float2*)&Pw[(qr + 8) * FST2 + ns * 8 + qc * 2] = p1;
                }
            }
            __syncwarp();

            #pragma unroll
            for (int kb = 0; kb < 8; kb++) {
                uint32_t pa[4];
                ldsm4(pa, aAddr + kb * 32);
                uint32_t bf[4][4];
                #pragma unroll
                for (int g = 0; g < 4; g++) ldsm4(bf[g], vAddr[g] + kb * 32);
                #pragma unroll
                for (int g = 0; g < 4; g++) {
                    mma_tf32(o[2 * g],     pa, bf[g][0], bf[g][1]);
                    mma_tf32(o[2 * g + 1], pa, bf[g][2], bf[g][3]);
                }
            }
        }
        __syncthreads();
    }

    #pragma unroll
    for (int hl = 0; hl < 2; hl++) {
        float inv = 1.f / l_i[hl];
        int rg = m0 + wm + qr + hl * 8;
        float* ob = out + (size_t)(b * T_ + rg) * C_ + h * D_;
        #pragma unroll
        for (int ns = 0; ns < 8; ns++) {
            float2 w = make_float2(o[ns][hl * 2 + 0] * inv, o[ns][hl * 2 + 1] * inv);
            *(float2*)&ob[ns * 8 + qc * 2] = w;
        }
    }
}

// ---------------------------------------------------------------------------
extern "C" void kernel_launch(void* const* d_in, const int* in_sizes, int n_in,
                              void* d_out, int out_size) {
    const float* x      = (const float*)d_in[0];
    const float* qkv_w  = (const float*)d_in[1];
    const float* qkv_b  = (const float*)d_in[2];
    const float* proj_w = (const float*)d_in[3];
    const float* proj_b = (const float*)d_in[4];
    const float* rel    = (const float*)d_in[5];
    float* out = (float*)d_out;

    float *p_qkv, *p_attn;
    cudaGetSymbolAddress((void**)&p_qkv, g_qkv);
    cudaGetSymbolAddress((void**)&p_attn, g_attn);

    static int attr_set = 0;
    if (!attr_set) {
        cudaFuncSetAttribute(gemm_tf32_nt_bias,
                             cudaFuncAttributeMaxDynamicSharedMemorySize, GEMM_SMEM);
        cudaFuncSetAttribute(flash_mma2_kernel,
                             cudaFuncAttributeMaxDynamicSharedMemorySize,
                             (int)(FLASH2_FLOATS * sizeof(float)));
        attr_set = 1;
    }

    // 1) bias table reduce (log2 domain)
    reduce_table_kernel<<<NPOS, 512>>>(rel);

    // 2) QKV projection (tf32 MMA, 64x64 warp tile, 2 CTAs/SM)
    {
        dim3 grid(L3C / TBN, (B_ * T_) / TBM);
        gemm_tf32_nt_bias<<<grid, 128, GEMM_SMEM>>>(x, qkv_w, qkv_b, p_qkv,
                                                    B_ * T_, L3C, C_);
    }

    // 3) fused flash attention (tf32 MMA + ldmatrix)
    {
        dim3 grid(T_ / 128, B_ * H_);
        flash_mma2_kernel<<<grid, 256, FLASH2_FLOATS * sizeof(float)>>>(p_attn);
    }

    // 4) output projection (tf32 MMA, 64x64 warp tile, 2 CTAs/SM)
    {
        dim3 grid(C_ / TBN, (B_ * T_) / TBM);
        gemm_tf32_nt_bias<<<grid, 128, GEMM_SMEM>>>(p_attn, proj_w, proj_b, out,
                                                    B_ * T_, C_, C_);
    }
}

// round 15
// speedup vs baseline: 1.0354x; 1.0354x over previous
#include <cuda_runtime.h>
#include <cuda_bf16.h>
#include <math.h>
#include <stdint.h>

// Shapes (fixed by the problem)
#define B_ 4
#define T_ 1024
#define C_ 1024
#define H_ 16
#define D_ 64
#define L3C (3 * C_)          // 3072
#define NPOS (2 * T_ - 1)     // 2047

// Scratch (allocation-free rule: __device__ globals)
__device__ float g_qkv[(size_t)B_ * T_ * L3C];   // (B*T, 3C) row-major
__device__ float g_attn[(size_t)B_ * T_ * C_];   // (B*T, C), tf32-rounded by flash
__device__ float g_table[NPOS * H_];             // (2L-1, H), pre-scaled by log2(e)
__device__ float g_x32[(size_t)B_ * T_ * C_];    // tf32-rounded x
__device__ float g_qw32[(size_t)L3C * C_];       // tf32-rounded qkv_w
__device__ float g_pw32[(size_t)C_ * C_];        // tf32-rounded proj_w

__device__ __forceinline__ uint32_t f2tf32(float x) {
    uint32_t u;
    asm("cvt.rna.tf32.f32 %0, %1;" : "=r"(u) : "f"(x));
    return u;
}
__device__ __forceinline__ float tf32rf(float x) { return __uint_as_float(f2tf32(x)); }

__device__ __forceinline__ float ex2f(float x) {
    float y;
    asm("ex2.approx.f32 %0, %1;" : "=f"(y) : "f"(x));
    return y;
}

__device__ __forceinline__ void mma_tf32(float* d, const uint32_t* a,
                                         uint32_t b0, uint32_t b1) {
    asm volatile(
        "mma.sync.aligned.m16n8k8.row.col.f32.tf32.tf32.f32 "
        "{%0,%1,%2,%3}, {%4,%5,%6,%7}, {%8,%9}, {%0,%1,%2,%3};\n"
        : "+f"(d[0]), "+f"(d[1]), "+f"(d[2]), "+f"(d[3])
        : "r"(a[0]), "r"(a[1]), "r"(a[2]), "r"(a[3]), "r"(b0), "r"(b1));
}

__device__ __forceinline__ void ldsm4(uint32_t* r, uint32_t saddr) {
    asm volatile(
        "ldmatrix.sync.aligned.m8n8.x4.shared.b16 {%0,%1,%2,%3}, [%4];\n"
        : "=r"(r[0]), "=r"(r[1]), "=r"(r[2]), "=r"(r[3]) : "r"(saddr));
}

// ---------------------------------------------------------------------------
// Kernel 0: elementwise tf32 rounding (pre-pass for GEMM operands)
// ---------------------------------------------------------------------------
__global__ __launch_bounds__(256) void tf32_convert_kernel(
    const float4* __restrict__ in, float4* __restrict__ out, int n4)
{
    int i = blockIdx.x * 256 + threadIdx.x;
    if (i < n4) {
        float4 v = in[i];
        out[i] = make_float4(tf32rf(v.x), tf32rf(v.y), tf32rf(v.z), tf32rf(v.w));
    }
}

// ---------------------------------------------------------------------------
// Kernel 1: reduce rel_pos_emb (2047,1024) -> table (2047,16), × log2(e)
// ---------------------------------------------------------------------------
__global__ __launch_bounds__(512) void reduce_table_kernel(const float* __restrict__ rel) {
    int row = blockIdx.x;
    int w   = threadIdx.x >> 5;
    int lane = threadIdx.x & 31;
    const float* p = rel + (size_t)row * C_ + w * D_;
    float s = p[lane] + p[lane + 32];
    #pragma unroll
    for (int off = 16; off > 0; off >>= 1)
        s += __shfl_xor_sync(0xffffffffu, s, off);
    if (lane == 0) g_table[row * H_ + w] = s * 1.4426950408889634f;
}

// ---------------------------------------------------------------------------
// Kernel 2: TF32 GEMM  C[M,N] = A[M,K] @ Bmat[N,K]^T + bias[N]
// Inputs pre-rounded to tf32 (staging is pure float4 copies — no cvt).
// CTA tile 128x256, 256 threads, 8 warps (2m x 4n), warp tile 64x64.
// TBK=16, register-prefetch double buffer, smem stride 20 floats.
// (R12 mainloop, staging de-fattened.)
// ---------------------------------------------------------------------------
#define TBM 128
#define TBN 256
#define TBK 16
#define GST 20
#define A_FLOATS (TBM * GST)               // 2560 floats per stage
#define B_FLOATS (TBN * GST)               // 5120 floats per stage
#define STG_FLOATS (A_FLOATS + B_FLOATS)   // 7680
#define GEMM_SMEM (2 * STG_FLOATS * 4)     // 61440 B

__global__ __launch_bounds__(256, 1) void gemm_tf32_nt_bias(
    const float* __restrict__ A, const float* __restrict__ Bm,
    const float* __restrict__ bias, float* __restrict__ Cout,
    int M, int N, int K)
{
    extern __shared__ float gsm[];
    const uint32_t smBase = (uint32_t)__cvta_generic_to_shared(gsm);

    const int tid  = threadIdx.x;
    const int lane = tid & 31;
    const int wid  = tid >> 5;
    const int wm   = (wid & 1) * 64;      // 2 warps in m
    const int wn   = (wid >> 1) * 64;     // 4 warps in n
    const int m0   = blockIdx.y * TBM;
    const int n0   = blockIdx.x * TBN;

    const int qr = lane >> 2;
    const int qc = lane & 3;

    // loaders
    const int lr = tid & 127;             // row within 128
    const int lh = tid >> 7;              // k-half (8 floats)

    const float* Aptr  = A  + (size_t)(m0 + lr) * K + lh * 8;
    const float* Bptr0 = Bm + (size_t)(n0 + lr) * K + lh * 8;
    const float* Bptr1 = Bm + (size_t)(n0 + 128 + lr) * K + lh * 8;

    float* As = gsm;                       // [row][k] stride GST
    float* Bs = gsm + A_FLOATS;

    // fragment base addresses (stage 0, bytes)
    const uint32_t aAddr = smBase + (((wm + (lane & 15)) * GST + (lane >> 4) * 4) << 2);
    const uint32_t bRow = (lane & 7) + ((lane >> 4) & 1) * 8;
    const uint32_t bCol = ((lane >> 3) & 1) * 4;
    uint32_t bAddr[4];
    #pragma unroll
    for (int g = 0; g < 4; g++)
        bAddr[g] = smBase + (A_FLOATS << 2)
                 + (((wn + 16 * g + bRow) * GST + bCol) << 2);

    float acc[4][8][4];
    #pragma unroll
    for (int i = 0; i < 4; i++)
        #pragma unroll
        for (int j = 0; j < 8; j++)
            #pragma unroll
            for (int r = 0; r < 4; r++) acc[i][j][r] = 0.f;

    float4 fa[2], fb0[2], fb1[2];
    // prefetch tile 0
    #pragma unroll
    for (int j = 0; j < 2; j++) {
        fa[j]  = *(const float4*)(Aptr  + j * 4);
        fb0[j] = *(const float4*)(Bptr0 + j * 4);
        fb1[j] = *(const float4*)(Bptr1 + j * 4);
    }
    // store tile 0 (pure copies — inputs already tf32-rounded)
    #pragma unroll
    for (int j = 0; j < 2; j++) {
        *(float4*)&As[lr * GST + lh * 8 + j * 4]         = fa[j];
        *(float4*)&Bs[lr * GST + lh * 8 + j * 4]         = fb0[j];
        *(float4*)&Bs[(128 + lr) * GST + lh * 8 + j * 4] = fb1[j];
    }
    __syncthreads();

    const int nIter = K / TBK;
    for (int t = 0; t < nIter; t++) {
        const int buf = t & 1;
        const uint32_t bo = (uint32_t)buf * (STG_FLOATS * 4);
        if (t + 1 < nIter) {
            const float* ap  = Aptr  + (t + 1) * TBK;
            const float* bp0 = Bptr0 + (t + 1) * TBK;
            const float* bp1 = Bptr1 + (t + 1) * TBK;
            #pragma unroll
            for (int j = 0; j < 2; j++) {
                fa[j]  = *(const float4*)(ap  + j * 4);
                fb0[j] = *(const float4*)(bp0 + j * 4);
                fb1[j] = *(const float4*)(bp1 + j * 4);
            }
        }

        #pragma unroll
        for (int ks = 0; ks < 2; ks++) {
            const uint32_t ko = bo + ks * 32;
            uint32_t af[4][4], bf[4][4];
            #pragma unroll
            for (int ms = 0; ms < 4; ms++)
                ldsm4(af[ms], aAddr + (uint32_t)(ms * 16 * GST * 4) + ko);
            #pragma unroll
            for (int g = 0; g < 4; g++) ldsm4(bf[g], bAddr[g] + ko);
            #pragma unroll
            for (int ms = 0; ms < 4; ms++)
                #pragma unroll
                for (int g = 0; g < 4; g++) {
                    mma_tf32(acc[ms][2 * g],     af[ms], bf[g][0], bf[g][1]);
                    mma_tf32(acc[ms][2 * g + 1], af[ms], bf[g][2], bf[g][3]);
                }
        }

        if (t + 1 < nIter) {
            const int nb = buf ^ 1;
            float* Asn = gsm + nb * STG_FLOATS;
            float* Bsn = Asn + A_FLOATS;
            #pragma unroll
            for (int j = 0; j < 2; j++) {
                *(float4*)&Asn[lr * GST + lh * 8 + j * 4]         = fa[j];
                *(float4*)&Bsn[lr * GST + lh * 8 + j * 4]         = fb0[j];
                *(float4*)&Bsn[(128 + lr) * GST + lh * 8 + j * 4] = fb1[j];
            }
        }
        __syncthreads();
    }

    // epilogue: + bias, write (float2 stores)
    #pragma unroll
    for (int ms = 0; ms < 4; ms++) {
        int r = m0 + wm + ms * 16 + qr;
        #pragma unroll
        for (int ns = 0; ns < 8; ns++) {
            int c = n0 + wn + ns * 8 + qc * 2;
            float b0 = bias[c], b1 = bias[c + 1];
            float2 v0 = make_float2(acc[ms][ns][0] + b0, acc[ms][ns][1] + b1);
            float2 v1 = make_float2(acc[ms][ns][2] + b0, acc[ms][ns][3] + b1);
            *(float2*)&Cout[(size_t)r * N + c]       = v0;
            *(float2*)&Cout[(size_t)(r + 8) * N + c] = v1;
        }
    }
}

// ---------------------------------------------------------------------------
// Kernel 3: TF32 MMA flash attention v2 (R12 verbatim except epilogue writes
// tf32-rounded attn so proj GEMM needs no cvt; bit-identical numerics).
// ---------------------------------------------------------------------------
#define FST2 68
#define FOFF_KS 0
#define FOFF_VT (64 * FST2)
#define FOFF_QP (2 * 64 * FST2)
#define FOFF_SB (FOFF_QP + 128 * FST2)
#define FLASH2_FLOATS (FOFF_SB + 192)

__global__ __launch_bounds__(256, 2) void flash_mma2_kernel(float* __restrict__ out) {
    extern __shared__ float sm[];
    float* Ks = sm + FOFF_KS;
    float* Vt = sm + FOFF_VT;
    float* QP = sm + FOFF_QP;
    float* sb = sm + FOFF_SB;

    const int bh = blockIdx.y;
    const int b  = bh >> 4;
    const int h  = bh & 15;
    const int m0 = blockIdx.x * 128;

    const int tid  = threadIdx.x;
    const int lane = tid & 31;
    const int wid  = tid >> 5;
    const int qr = lane >> 2;
    const int qc = lane & 3;
    const int wm = wid * 16;

    {
        const float qsc = 0.125f * 1.4426950408889634f;
        const float* qb = g_qkv + (size_t)(b * T_ + m0) * L3C + h * D_;
        #pragma unroll
        for (int i = 0; i < 8; i++) {
            int f = tid + i * 256;
            int row = f >> 4, c4 = (f & 15) * 4;
            float4 v = *(const float4*)(qb + (size_t)row * L3C + c4);
            float4 w = make_float4(tf32rf(v.x * qsc), tf32rf(v.y * qsc),
                                   tf32rf(v.z * qsc), tf32rf(v.w * qsc));
            *(float4*)&QP[row * FST2 + c4] = w;
        }
    }
    __syncthreads();

    const uint32_t aAddr = (uint32_t)__cvta_generic_to_shared(QP)
        + (((wm + (lane & 15)) * FST2 + (lane >> 4) * 4) << 2);
    uint32_t qf[8][4];
    #pragma unroll
    for (int kb = 0; kb < 8; kb++) ldsm4(qf[kb], aAddr + kb * 32);

    const uint32_t bRow = (lane & 7) + ((lane >> 4) & 1) * 8;
    const uint32_t bCol = ((lane >> 3) & 1) * 4;
    uint32_t kAddr[4], vAddr[4];
    {
        const uint32_t kBase = (uint32_t)__cvta_generic_to_shared(Ks);
        const uint32_t vBase = (uint32_t)__cvta_generic_to_shared(Vt);
        #pragma unroll
        for (int g = 0; g < 4; g++) {
            kAddr[g] = kBase + (((16 * g + bRow) * FST2 + bCol) << 2);
            vAddr[g] = vBase + (((16 * g + bRow) * FST2 + bCol) << 2);
        }
    }

    float m_i[2] = {-1e30f, -1e30f};
    float l_i[2] = {0.f, 0.f};
    float o[8][4];
    #pragma unroll
    for (int ns = 0; ns < 8; ns++)
        #pragma unroll
        for (int r = 0; r < 4; r++) o[ns][r] = 0.f;

    const float* kgb = g_qkv + (size_t)(b * T_) * L3C + C_ + h * D_;
    const float* vgb = kgb + C_;

    const int ntiles = 2 * blockIdx.x + 2;
    for (int t = 0; t < ntiles; t++) {
        const int j0 = t * 64;
        #pragma unroll
        for (int i = 0; i < 4; i++) {
            int f = tid + i * 256;
            int row = f >> 4, c4 = (f & 15) * 4;
            float4 kv = *(const float4*)(kgb + (size_t)(j0 + row) * L3C + c4);
            float4 w = make_float4(tf32rf(kv.x), tf32rf(kv.y), tf32rf(kv.z), tf32rf(kv.w));
            *(float4*)&Ks[row * FST2 + c4] = w;
        }
        {
            const int d  = tid & 63;
            const int kq = tid >> 6;
            #pragma unroll
            for (int c = 0; c < 4; c++) {
                int key4 = kq * 4 + c * 16;
                const float* vp = vgb + (size_t)(j0 + key4) * L3C + d;
                float4 w = make_float4(tf32rf(vp[0]),
                                       tf32rf(vp[(size_t)L3C]),
                                       tf32rf(vp[(size_t)2 * L3C]),
                                       tf32rf(vp[(size_t)3 * L3C]));
                *(float4*)&Vt[d * FST2 + key4] = w;
            }
        }
        if (tid < 191) sb[tid] = g_table[(m0 - j0 + 960 + tid) * H_ + h];
        __syncthreads();

        const int rel = j0 - m0;
        if (rel <= wm + 15) {
            float sacc[8][4];
            #pragma unroll
            for (int ns = 0; ns < 8; ns++)
                #pragma unroll
                for (int r = 0; r < 4; r++) sacc[ns][r] = 0.f;

            #pragma unroll
            for (int kb = 0; kb < 8; kb++) {
                uint32_t bf[4][4];
                #pragma unroll
                for (int g = 0; g < 4; g++) ldsm4(bf[g], kAddr[g] + kb * 32);
                #pragma unroll
                for (int g = 0; g < 4; g++) {
                    mma_tf32(sacc[2 * g],     qf[kb], bf[g][0], bf[g][1]);
                    mma_tf32(sacc[2 * g + 1], qf[kb], bf[g][2], bf[g][3]);
                }
            }

            const bool tail = (rel >= 0);
            #pragma unroll
            for (int hl = 0; hl < 2; hl++) {
                const int rloc = wm + qr + hl * 8;
                float mx = -1e30f;
                #pragma unroll
                for (int ns = 0; ns < 8; ns++) {
                    #pragma unroll
                    for (int j2 = 0; j2 < 2; j2++) {
                        int col = ns * 8 + qc * 2 + j2;
                        float v = sacc[ns][hl * 2 + j2] + sb[rloc - col + 63];
                        if (tail && col + rel > rloc) v = -1e30f;
                        sacc[ns][hl * 2 + j2] = v;
                        mx = fmaxf(mx, v);
                    }
                }
                mx = fmaxf(mx, __shfl_xor_sync(0xffffffffu, mx, 1));
                mx = fmaxf(mx, __shfl_xor_sync(0xffffffffu, mx, 2));
                float mnew = fmaxf(m_i[hl], mx);
                float corr = ex2f(m_i[hl] - mnew);
                float rs = 0.f;
                #pragma unroll
                for (int ns = 0; ns < 8; ns++) {
                    #pragma unroll
                    for (int j2 = 0; j2 < 2; j2++) {
                        float p = ex2f(sacc[ns][hl * 2 + j2] - mnew);
                        sacc[ns][hl * 2 + j2] = p;
                        rs += p;
                    }
                }
                rs += __shfl_xor_sync(0xffffffffu, rs, 1);
                rs += __shfl_xor_sync(0xffffffffu, rs, 2);
                l_i[hl] = l_i[hl] * corr + rs;
                m_i[hl] = mnew;
                #pragma unroll
                for (int ns = 0; ns < 8; ns++) {
                    o[ns][hl * 2 + 0] *= corr;
                    o[ns][hl * 2 + 1] *= corr;
                }
            }

            {
                float* Pw = QP + wm * FST2;
                #pragma unroll
                for (int ns = 0; ns < 8; ns++) {
                    float2 p0 = make_float2(tf32rf(sacc[ns][0]), tf32rf(sacc[ns][1]));
                    float2 p1 = make_float2(tf32rf(sacc[ns][2]), tf32rf(sacc[ns][3]));
                    *(float2*)&Pw[qr * FST2 + ns * 8 + qc * 2] = p0;
                    *(float2*)&Pw[(qr + 8) * FST2 + ns * 8 + qc * 2] = p1;
                }
            }
            __syncwarp();

            #pragma unroll
            for (int kb = 0; kb < 8; kb++) {
                uint32_t pa[4];
                ldsm4(pa, aAddr + kb * 32);
                uint32_t bf[4][4];
                #pragma unroll
                for (int g = 0; g < 4; g++) ldsm4(bf[g], vAddr[g] + kb * 32);
                #pragma unroll
                for (int g = 0; g < 4; g++) {
                    mma_tf32(o[2 * g],     pa, bf[g][0], bf[g][1]);
                    mma_tf32(o[2 * g + 1], pa, bf[g][2], bf[g][3]);
                }
            }
        }
        __syncthreads();
    }

    // epilogue: normalize, tf32-round (feeds proj GEMM), write (B,T,H*D)
    #pragma unroll
    for (int hl = 0; hl < 2; hl++) {
        float inv = 1.f / l_i[hl];
        int rg = m0 + wm + qr + hl * 8;
        float* ob = out + (size_t)(b * T_ + rg) * C_ + h * D_;
        #pragma unroll
        for (int ns = 0; ns < 8; ns++) {
            float2 w = make_float2(tf32rf(o[ns][hl * 2 + 0] * inv),
                                   tf32rf(o[ns][hl * 2 + 1] * inv));
            *(float2*)&ob[ns * 8 + qc * 2] = w;
        }
    }
}

// ---------------------------------------------------------------------------
extern "C" void kernel_launch(void* const* d_in, const int* in_sizes, int n_in,
                              void* d_out, int out_size) {
    const float* x      = (const float*)d_in[0];
    const float* qkv_w  = (const float*)d_in[1];
    const float* qkv_b  = (const float*)d_in[2];
    const float* proj_w = (const float*)d_in[3];
    const float* proj_b = (const float*)d_in[4];
    const float* rel    = (const float*)d_in[5];
    float* out = (float*)d_out;

    float *p_qkv, *p_attn, *p_x32, *p_qw32, *p_pw32;
    cudaGetSymbolAddress((void**)&p_qkv, g_qkv);
    cudaGetSymbolAddress((void**)&p_attn, g_attn);
    cudaGetSymbolAddress((void**)&p_x32, g_x32);
    cudaGetSymbolAddress((void**)&p_qw32, g_qw32);
    cudaGetSymbolAddress((void**)&p_pw32, g_pw32);

    static int attr_set = 0;
    if (!attr_set) {
        cudaFuncSetAttribute(gemm_tf32_nt_bias,
                             cudaFuncAttributeMaxDynamicSharedMemorySize, GEMM_SMEM);
        cudaFuncSetAttribute(flash_mma2_kernel,
                             cudaFuncAttributeMaxDynamicSharedMemorySize,
                             (int)(FLASH2_FLOATS * sizeof(float)));
        attr_set = 1;
    }

    // 0) tf32 pre-rounding of GEMM operands
    {
        int n4x = (B_ * T_ * C_) / 4;
        tf32_convert_kernel<<<n4x / 256, 256>>>((const float4*)x, (float4*)p_x32, n4x);
        int n4q = (L3C * C_) / 4;
        tf32_convert_kernel<<<n4q / 256, 256>>>((const float4*)qkv_w, (float4*)p_qw32, n4q);
        int n4p = (C_ * C_) / 4;
        tf32_convert_kernel<<<n4p / 256, 256>>>((const float4*)proj_w, (float4*)p_pw32, n4p);
    }

    // 1) bias table reduce (log2 domain)
    reduce_table_kernel<<<NPOS, 512>>>(rel);

    // 2) QKV projection (tf32 MMA, 64x64 warp tile, cvt-free staging)
    {
        dim3 grid(L3C / TBN, (B_ * T_) / TBM);
        gemm_tf32_nt_bias<<<grid, 256, GEMM_SMEM>>>(p_x32, p_qw32, qkv_b, p_qkv,
                                                    B_ * T_, L3C, C_);
    }

    // 3) fused flash attention (tf32 MMA + ldmatrix)
    {
        dim3 grid(T_ / 128, B_ * H_);
        flash_mma2_kernel<<<grid, 256, FLASH2_FLOATS * sizeof(float)>>>(p_attn);
    }

    // 4) output projection (tf32 MMA, 64x64 warp tile, cvt-free staging)
    {
        dim3 grid(C_ / TBN, (B_ * T_) / TBM);
        gemm_tf32_nt_bias<<<grid, 256, GEMM_SMEM>>>(p_attn, p_pw32, proj_b, out,
                                                    B_ * T_, C_, C_);
    }
}

// round 17
// speedup vs baseline: 1.8624x; 1.7987x over previous
#include <cuda_runtime.h>
#include <cuda_fp16.h>
#include <math.h>
#include <stdint.h>

// Shapes (fixed by the problem)
#define B_ 4
#define T_ 1024
#define C_ 1024
#define H_ 16
#define D_ 64
#define L3C (3 * C_)          // 3072
#define NPOS (2 * T_ - 1)     // 2047

// Scratch (allocation-free rule: __device__ globals)
__device__ __half g_qkvh[(size_t)B_ * T_ * L3C];  // (B*T, 3C) fp16
__device__ __half g_attnh[(size_t)B_ * T_ * C_];  // (B*T, C) fp16
__device__ float  g_table[NPOS * H_];             // (2L-1, H), × log2(e)
__device__ __half g_x16[(size_t)B_ * T_ * C_];    // fp16 x
__device__ __half g_qw16[(size_t)L3C * C_];       // fp16 qkv_w
__device__ __half g_pw16[(size_t)C_ * C_];        // fp16 proj_w

__device__ __forceinline__ float ex2f(float x) {
    float y;
    asm("ex2.approx.f32 %0, %1;" : "=f"(y) : "f"(x));
    return y;
}

__device__ __forceinline__ void mma_f16(float* d, const uint32_t* a,
                                        uint32_t b0, uint32_t b1) {
    asm volatile(
        "mma.sync.aligned.m16n8k16.row.col.f32.f16.f16.f32 "
        "{%0,%1,%2,%3}, {%4,%5,%6,%7}, {%8,%9}, {%0,%1,%2,%3};\n"
        : "+f"(d[0]), "+f"(d[1]), "+f"(d[2]), "+f"(d[3])
        : "r"(a[0]), "r"(a[1]), "r"(a[2]), "r"(a[3]), "r"(b0), "r"(b1));
}

__device__ __forceinline__ void ldsm4(uint32_t* r, uint32_t saddr) {
    asm volatile(
        "ldmatrix.sync.aligned.m8n8.x4.shared.b16 {%0,%1,%2,%3}, [%4];\n"
        : "=r"(r[0]), "=r"(r[1]), "=r"(r[2]), "=r"(r[3]) : "r"(saddr));
}

__device__ __forceinline__ void ldsm4t(uint32_t* r, uint32_t saddr) {
    asm volatile(
        "ldmatrix.sync.aligned.m8n8.x4.trans.shared.b16 {%0,%1,%2,%3}, [%4];\n"
        : "=r"(r[0]), "=r"(r[1]), "=r"(r[2]), "=r"(r[3]) : "r"(saddr));
}

// ---------------------------------------------------------------------------
// Kernel 0: fp32 -> fp16 conversion (pre-pass for GEMM operands)
// ---------------------------------------------------------------------------
__global__ __launch_bounds__(256) void f32_to_f16_kernel(
    const float4* __restrict__ in, __half2* __restrict__ out, int n4)
{
    int i = blockIdx.x * 256 + threadIdx.x;
    if (i < n4) {
        float4 v = in[i];
        out[2 * i + 0] = __floats2half2_rn(v.x, v.y);
        out[2 * i + 1] = __floats2half2_rn(v.z, v.w);
    }
}

// ---------------------------------------------------------------------------
// Kernel 1: reduce rel_pos_emb (2047,1024) -> table (2047,16), × log2(e)
// ---------------------------------------------------------------------------
__global__ __launch_bounds__(512) void reduce_table_kernel(const float* __restrict__ rel) {
    int row = blockIdx.x;
    int w   = threadIdx.x >> 5;
    int lane = threadIdx.x & 31;
    const float* p = rel + (size_t)row * C_ + w * D_;
    float s = p[lane] + p[lane + 32];
    #pragma unroll
    for (int off = 16; off > 0; off >>= 1)
        s += __shfl_xor_sync(0xffffffffu, s, off);
    if (lane == 0) g_table[row * H_ + w] = s * 1.4426950408889634f;
}

// ---------------------------------------------------------------------------
// Kernel 2: FP16 GEMM  C[M,N] = A[M,K] @ Bmat[N,K]^T + bias[N]
// m16n8k16 MMA (fp32 accum). CTA tile 128x256, 256 threads, 8 warps
// (2m x 4n), warp tile 64x64. TBK=32 halfs, register-prefetch double
// buffer, smem rows stride 40 halfs (80B = 5x16B: ldsm + STS conflict-free).
// HOUT: write __half output (QKV) or float output (proj).
// ---------------------------------------------------------------------------
#define TBM 128
#define TBN 256
#define TBK 32
#define GSTH 40                            // halfs per row (32 data + 8 pad)
#define A_HALFS (TBM * GSTH)               // 5120
#define B_HALFS (TBN * GSTH)               // 10240
#define STG_HALFS (A_HALFS + B_HALFS)      // 15360
#define GEMM_SMEM (2 * STG_HALFS * 2)      // 61440 B

template<bool HOUT>
__global__ __launch_bounds__(256, 1) void gemm_f16_nt_bias(
    const __half* __restrict__ A, const __half* __restrict__ Bm,
    const float* __restrict__ bias, void* __restrict__ Cv,
    int M, int N, int K)
{
    extern __shared__ __half gsmh[];
    const uint32_t smBase = (uint32_t)__cvta_generic_to_shared(gsmh);

    const int tid  = threadIdx.x;
    const int lane = tid & 31;
    const int wid  = tid >> 5;
    const int wm   = (wid & 1) * 64;      // 2 warps in m
    const int wn   = (wid >> 1) * 64;     // 4 warps in n
    const int m0   = blockIdx.y * TBM;
    const int n0   = blockIdx.x * TBN;

    const int qr = lane >> 2;
    const int qc = lane & 3;

    // loaders: thread covers row lr, k-half lh (16 halfs = 32B = 2 x uint4)
    const int lr = tid & 127;
    const int lh = tid >> 7;

    const __half* Aptr  = A  + (size_t)(m0 + lr) * K + lh * 16;
    const __half* Bptr0 = Bm + (size_t)(n0 + lr) * K + lh * 16;
    const __half* Bptr1 = Bm + (size_t)(n0 + 128 + lr) * K + lh * 16;

    __half* As = gsmh;                     // [row][k] stride GSTH
    __half* Bs = gsmh + A_HALFS;

    // fragment base addresses (stage 0, bytes)
    const uint32_t aAddr = smBase + ((wm + (lane & 15)) * GSTH * 2) + (lane >> 4) * 16;
    uint32_t bAddr[4];
    #pragma unroll
    for (int g = 0; g < 4; g++)
        bAddr[g] = smBase + A_HALFS * 2
                 + ((wn + 16 * g + (lane & 7) + ((lane >> 4) & 1) * 8) * GSTH * 2)
                 + ((lane >> 3) & 1) * 16;

    float acc[4][8][4];
    #pragma unroll
    for (int i = 0; i < 4; i++)
        #pragma unroll
        for (int j = 0; j < 8; j++)
            #pragma unroll
            for (int r = 0; r < 4; r++) acc[i][j][r] = 0.f;

    uint4 fa[2], fb0[2], fb1[2];
    #pragma unroll
    for (int j = 0; j < 2; j++) {
        fa[j]  = *(const uint4*)(Aptr  + j * 8);
        fb0[j] = *(const uint4*)(Bptr0 + j * 8);
        fb1[j] = *(const uint4*)(Bptr1 + j * 8);
    }
    #pragma unroll
    for (int j = 0; j < 2; j++) {
        *(uint4*)&As[lr * GSTH + lh * 16 + j * 8]         = fa[j];
        *(uint4*)&Bs[lr * GSTH + lh * 16 + j * 8]         = fb0[j];
        *(uint4*)&Bs[(128 + lr) * GSTH + lh * 16 + j * 8] = fb1[j];
    }
    __syncthreads();

    const int nIter = K / TBK;            // 32
    for (int t = 0; t < nIter; t++) {
        const int buf = t & 1;
        const uint32_t bo = (uint32_t)buf * (STG_HALFS * 2);
        if (t + 1 < nIter) {
            const __half* ap  = Aptr  + (t + 1) * TBK;
            const __half* bp0 = Bptr0 + (t + 1) * TBK;
            const __half* bp1 = Bptr1 + (t + 1) * TBK;
            #pragma unroll
            for (int j = 0; j < 2; j++) {
                fa[j]  = *(const uint4*)(ap  + j * 8);
                fb0[j] = *(const uint4*)(bp0 + j * 8);
                fb1[j] = *(const uint4*)(bp1 + j * 8);
            }
        }

        #pragma unroll
        for (int ks = 0; ks < 2; ks++) {
            const uint32_t ko = bo + ks * 32;   // 16 halfs = 32 B
            uint32_t af[4][4], bf[4][4];
            #pragma unroll
            for (int ms = 0; ms < 4; ms++)
                ldsm4(af[ms], aAddr + (uint32_t)(ms * 16 * GSTH * 2) + ko);
            #pragma unroll
            for (int g = 0; g < 4; g++) ldsm4(bf[g], bAddr[g] + ko);
            #pragma unroll
            for (int ms = 0; ms < 4; ms++)
                #pragma unroll
                for (int g = 0; g < 4; g++) {
                    mma_f16(acc[ms][2 * g],     af[ms], bf[g][0], bf[g][1]);
                    mma_f16(acc[ms][2 * g + 1], af[ms], bf[g][2], bf[g][3]);
                }
        }

        if (t + 1 < nIter) {
            const int nb = buf ^ 1;
            __half* Asn = gsmh + nb * STG_HALFS;
            __half* Bsn = Asn + A_HALFS;
            #pragma unroll
            for (int j = 0; j < 2; j++) {
                *(uint4*)&Asn[lr * GSTH + lh * 16 + j * 8]         = fa[j];
                *(uint4*)&Bsn[lr * GSTH + lh * 16 + j * 8]         = fb0[j];
                *(uint4*)&Bsn[(128 + lr) * GSTH + lh * 16 + j * 8] = fb1[j];
            }
        }
        __syncthreads();
    }

    // epilogue: + bias (fp32), write half2 or float2
    #pragma unroll
    for (int ms = 0; ms < 4; ms++) {
        int r = m0 + wm + ms * 16 + qr;
        #pragma unroll
        for (int ns = 0; ns < 8; ns++) {
            int c = n0 + wn + ns * 8 + qc * 2;
            float b0 = bias[c], b1 = bias[c + 1];
            float v00 = acc[ms][ns][0] + b0, v01 = acc[ms][ns][1] + b1;
            float v10 = acc[ms][ns][2] + b0, v11 = acc[ms][ns][3] + b1;
            if (HOUT) {
                __half* Ch = (__half*)Cv;
                *(__half2*)&Ch[(size_t)r * N + c]       = __floats2half2_rn(v00, v01);
                *(__half2*)&Ch[(size_t)(r + 8) * N + c] = __floats2half2_rn(v10, v11);
            } else {
                float* Cf = (float*)Cv;
                *(float2*)&Cf[(size_t)r * N + c]       = make_float2(v00, v01);
                *(float2*)&Cf[(size_t)(r + 8) * N + c] = make_float2(v10, v11);
            }
        }
    }
}

// ---------------------------------------------------------------------------
// Kernel 3: FP16 MMA flash attention. Grid (T/128, B*H), 256 threads,
// 8 warps x 16 query rows, 64-key tiles. log2-domain softmax (fp32).
// smem halfs, stride 72 (144B = 9x16B: conflict-free). V B-frags via
// ldmatrix.trans on natural [key][d] layout.
// ---------------------------------------------------------------------------
#define FSH 72
#define HOFF_KS 0
#define HOFF_VS (64 * FSH)                 // 4608 halfs
#define HOFF_QP (2 * 64 * FSH)             // 9216 halfs
#define HOFF_END (HOFF_QP + 128 * FSH)     // 18432 halfs (36864 B)
#define FLASH_SMEM_BYTES (HOFF_END * 2 + 192 * 4)

__global__ __launch_bounds__(256, 2) void flash_f16_kernel(__half* __restrict__ out) {
    extern __shared__ __half smh[];
    __half* Ks = smh + HOFF_KS;   // [key][d]
    __half* Vs = smh + HOFF_VS;   // [key][d]
    __half* QP = smh + HOFF_QP;   // [row][d] Q, later [row][key] P
    float*  sb = (float*)(smh + HOFF_END);

    const int bh = blockIdx.y;
    const int b  = bh >> 4;
    const int h  = bh & 15;
    const int m0 = blockIdx.x * 128;

    const int tid  = threadIdx.x;
    const int lane = tid & 31;
    const int wid  = tid >> 5;
    const int qr = lane >> 2;
    const int qc = lane & 3;
    const int wm = wid * 16;

    // stage Q: scale in fp32 by (1/8)*log2(e), round to fp16
    {
        const float qsc = 0.125f * 1.4426950408889634f;
        const __half* qb = g_qkvh + (size_t)(b * T_ + m0) * L3C + h * D_;
        #pragma unroll
        for (int i = 0; i < 4; i++) {
            int f = tid + i * 256;
            int row = f >> 3, c8 = (f & 7) * 8;
            uint4 v = *(const uint4*)(qb + (size_t)row * L3C + c8);
            __half2* hv = (__half2*)&v;
            #pragma unroll
            for (int j = 0; j < 4; j++) {
                float2 fv = __half22float2(hv[j]);
                hv[j] = __floats2half2_rn(fv.x * qsc, fv.y * qsc);
            }
            *(uint4*)&QP[row * FSH + c8] = v;
        }
    }
    __syncthreads();

    // Q A-fragments (4 k16 steps), loop-invariant; QP then reused for P
    const uint32_t aAddr = (uint32_t)__cvta_generic_to_shared(QP)
        + ((wm + (lane & 15)) * FSH * 2) + (lane >> 4) * 16;
    uint32_t qf[4][4];
    #pragma unroll
    for (int kb = 0; kb < 4; kb++) ldsm4(qf[kb], aAddr + kb * 32);

    // K B-frag addresses (non-trans) and V B-frag addresses (trans)
    uint32_t kAddr[4], vAddr[4];
    {
        const uint32_t kBase = (uint32_t)__cvta_generic_to_shared(Ks);
        const uint32_t vBase = (uint32_t)__cvta_generic_to_shared(Vs);
        #pragma unroll
        for (int g = 0; g < 4; g++) {
            kAddr[g] = kBase
                + ((16 * g + (lane & 7) + ((lane >> 4) & 1) * 8) * FSH * 2)
                + ((lane >> 3) & 1) * 16;
            // V (trans): g indexes d-pair group; kb adds key rows
            vAddr[g] = vBase
                + (((lane & 7) + ((lane >> 3) & 1) * 8) * FSH * 2)
                + g * 32 + ((lane >> 4) & 1) * 16;
        }
    }

    float m_i[2] = {-1e30f, -1e30f};
    float l_i[2] = {0.f, 0.f};
    float o[8][4];
    #pragma unroll
    for (int ns = 0; ns < 8; ns++)
        #pragma unroll
        for (int r = 0; r < 4; r++) o[ns][r] = 0.f;

    const __half* kgb = g_qkvh + (size_t)(b * T_) * L3C + C_ + h * D_;
    const __half* vgb = kgb + C_;

    const int ntiles = 2 * blockIdx.x + 2;
    for (int t = 0; t < ntiles; t++) {
        const int j0 = t * 64;
        // stage K, V: pure 16B copies (already fp16)
        #pragma unroll
        for (int i = 0; i < 2; i++) {
            int f = tid + i * 256;
            int row = f >> 3, c8 = (f & 7) * 8;
            *(uint4*)&Ks[row * FSH + c8] =
                *(const uint4*)(kgb + (size_t)(j0 + row) * L3C + c8);
            *(uint4*)&Vs[row * FSH + c8] =
                *(const uint4*)(vgb + (size_t)(j0 + row) * L3C + c8);
        }
        if (tid < 191) sb[tid] = g_table[(m0 - j0 + 960 + tid) * H_ + h];
        __syncthreads();

        const int rel = j0 - m0;
        if (rel <= wm + 15) {   // warp not fully masked
            // S = Q @ K^T (log2 domain)
            float sacc[8][4];
            #pragma unroll
            for (int ns = 0; ns < 8; ns++)
                #pragma unroll
                for (int r = 0; r < 4; r++) sacc[ns][r] = 0.f;

            #pragma unroll
            for (int kb = 0; kb < 4; kb++) {
                uint32_t bf[4][4];
                #pragma unroll
                for (int g = 0; g < 4; g++) ldsm4(bf[g], kAddr[g] + kb * 32);
                #pragma unroll
                for (int g = 0; g < 4; g++) {
                    mma_f16(sacc[2 * g],     qf[kb], bf[g][0], bf[g][1]);
                    mma_f16(sacc[2 * g + 1], qf[kb], bf[g][2], bf[g][3]);
                }
            }

            // bias + causal mask + online softmax (fp32)
            const bool tail = (rel >= 0);
            #pragma unroll
            for (int hl = 0; hl < 2; hl++) {
                const int rloc = wm + qr + hl * 8;
                float mx = -1e30f;
                #pragma unroll
                for (int ns = 0; ns < 8; ns++) {
                    #pragma unroll
                    for (int j2 = 0; j2 < 2; j2++) {
                        int col = ns * 8 + qc * 2 + j2;
                        float v = sacc[ns][hl * 2 + j2] + sb[rloc - col + 63];
                        if (tail && col + rel > rloc) v = -1e30f;
                        sacc[ns][hl * 2 + j2] = v;
                        mx = fmaxf(mx, v);
                    }
                }
                mx = fmaxf(mx, __shfl_xor_sync(0xffffffffu, mx, 1));
                mx = fmaxf(mx, __shfl_xor_sync(0xffffffffu, mx, 2));
                float mnew = fmaxf(m_i[hl], mx);
                float corr = ex2f(m_i[hl] - mnew);
                float rs = 0.f;
                #pragma unroll
                for (int ns = 0; ns < 8; ns++) {
                    #pragma unroll
                    for (int j2 = 0; j2 < 2; j2++) {
                        float p = ex2f(sacc[ns][hl * 2 + j2] - mnew);
                        sacc[ns][hl * 2 + j2] = p;
                        rs += p;
                    }
                }
                rs += __shfl_xor_sync(0xffffffffu, rs, 1);
                rs += __shfl_xor_sync(0xffffffffu, rs, 2);
                l_i[hl] = l_i[hl] * corr + rs;
                m_i[hl] = mnew;
                #pragma unroll
                for (int ns = 0; ns < 8; ns++) {
                    o[ns][hl * 2 + 0] *= corr;
                    o[ns][hl * 2 + 1] *= corr;
                }
            }

            // stage P (fp16) into this warp's own 16-row slice of QP
            {
                __half* Pw = QP + wm * FSH;
                #pragma unroll
                for (int ns = 0; ns < 8; ns++) {
                    *(__half2*)&Pw[qr * FSH + ns * 8 + qc * 2] =
                        __floats2half2_rn(sacc[ns][0], sacc[ns][1]);
                    *(__half2*)&Pw[(qr + 8) * FSH + ns * 8 + qc * 2] =
                        __floats2half2_rn(sacc[ns][2], sacc[ns][3]);
                }
            }
            __syncwarp();

            // O += P @ V  (A-frags from P; B-frags via trans-ldsm on Vs)
            #pragma unroll
            for (int kb = 0; kb < 4; kb++) {
                uint32_t pa[4];
                ldsm4(pa, aAddr + kb * 32);
                uint32_t vf[4][4];
                #pragma unroll
                for (int g = 0; g < 4; g++)
                    ldsm4t(vf[g], vAddr[g] + (uint32_t)(kb * 16 * FSH * 2));
                #pragma unroll
                for (int g = 0; g < 4; g++) {
                    mma_f16(o[2 * g],     pa, vf[g][0], vf[g][1]);
                    mma_f16(o[2 * g + 1], pa, vf[g][2], vf[g][3]);
                }
            }
        }
        __syncthreads();
    }

    // epilogue: normalize (fp32), write fp16 attn (feeds proj GEMM)
    #pragma unroll
    for (int hl = 0; hl < 2; hl++) {
        float inv = 1.f / l_i[hl];
        int rg = m0 + wm + qr + hl * 8;
        __half* ob = out + (size_t)(b * T_ + rg) * C_ + h * D_;
        #pragma unroll
        for (int ns = 0; ns < 8; ns++) {
            *(__half2*)&ob[ns * 8 + qc * 2] =
                __floats2half2_rn(o[ns][hl * 2 + 0] * inv, o[ns][hl * 2 + 1] * inv);
        }
    }
}

// ---------------------------------------------------------------------------
extern "C" void kernel_launch(void* const* d_in, const int* in_sizes, int n_in,
                              void* d_out, int out_size) {
    const float* x      = (const float*)d_in[0];
    const float* qkv_w  = (const float*)d_in[1];
    const float* qkv_b  = (const float*)d_in[2];
    const float* proj_w = (const float*)d_in[3];
    const float* proj_b = (const float*)d_in[4];
    const float* rel    = (const float*)d_in[5];
    float* out = (float*)d_out;

    __half *p_qkvh, *p_attnh, *p_x16, *p_qw16, *p_pw16;
    cudaGetSymbolAddress((void**)&p_qkvh, g_qkvh);
    cudaGetSymbolAddress((void**)&p_attnh, g_attnh);
    cudaGetSymbolAddress((void**)&p_x16, g_x16);
    cudaGetSymbolAddress((void**)&p_qw16, g_qw16);
    cudaGetSymbolAddress((void**)&p_pw16, g_pw16);

    static int attr_set = 0;
    if (!attr_set) {
        cudaFuncSetAttribute(gemm_f16_nt_bias<true>,
                             cudaFuncAttributeMaxDynamicSharedMemorySize, GEMM_SMEM);
        cudaFuncSetAttribute(gemm_f16_nt_bias<false>,
                             cudaFuncAttributeMaxDynamicSharedMemorySize, GEMM_SMEM);
        cudaFuncSetAttribute(flash_f16_kernel,
                             cudaFuncAttributeMaxDynamicSharedMemorySize,
                             FLASH_SMEM_BYTES);
        attr_set = 1;
    }

    // 0) fp32 -> fp16 pre-pass for GEMM operands
    {
        int n4x = (B_ * T_ * C_) / 4;
        f32_to_f16_kernel<<<n4x / 256, 256>>>((const float4*)x, (__half2*)p_x16, n4x);
        int n4q = (L3C * C_) / 4;
        f32_to_f16_kernel<<<n4q / 256, 256>>>((const float4*)qkv_w, (__half2*)p_qw16, n4q);
        int n4p = (C_ * C_) / 4;
        f32_to_f16_kernel<<<n4p / 256, 256>>>((const float4*)proj_w, (__half2*)p_pw16, n4p);
    }

    // 1) bias table reduce (log2 domain)
    reduce_table_kernel<<<NPOS, 512>>>(rel);

    // 2) QKV projection (fp16 MMA m16n8k16, half output)
    {
        dim3 grid(L3C / TBN, (B_ * T_) / TBM);
        gemm_f16_nt_bias<true><<<grid, 256, GEMM_SMEM>>>(
            p_x16, p_qw16, qkv_b, (void*)p_qkvh, B_ * T_, L3C, C_);
    }

    // 3) fused flash attention (fp16 MMA)
    {
        dim3 grid(T_ / 128, B_ * H_);
        flash_f16_kernel<<<grid, 256, FLASH_SMEM_BYTES>>>(p_attnh);
    }

    // 4) output projection (fp16 MMA, float output)
    {
        dim3 grid(C_ / TBN, (B_ * T_) / TBM);
        gemm_f16_nt_bias<false><<<grid, 256, GEMM_SMEM>>>(
            p_attnh, p_pw16, proj_b, (void*)out, B_ * T_, C_, C_);
    }
}